// round 16
// baseline (speedup 1.0000x reference)
#include <cuda_runtime.h>
#include <cuda_fp16.h>
#include <cstdint>

typedef unsigned long long ULL;

#define NPAD 704
#define PART2 (2048L * NPAD)

// ---------------- scratch (static device arrays; no runtime alloc) ----------
__device__ __half g_Ah[2048L * 2048];          // fp16 of concat(x,feature)  8MB
__device__ __half g_Bh[2048L * NPAD];          // fp16 [Wep1^T | Wp1 fold | 0]
__device__ float g_part[3 * PART2];            // K-split partial outputs
__device__ uint32_t g_W1zf[512 * 16];          // frag-ordered W1z (per warp/lane)
__device__ uint32_t g_W2f[512 * 16];           // frag-ordered Wep2

// ---------------- helpers ----------------------------------------------------
__device__ __forceinline__ uint32_t smem_u32(const void* p) {
    uint32_t a;
    asm("{ .reg .u64 t; cvta.to.shared.u64 t, %1; cvt.u32.u64 %0, t; }" : "=r"(a) : "l"(p));
    return a;
}
__device__ __forceinline__ uint32_t packh2(__half a, __half b) {
    __half2 p = __halves2half2(a, b);
    return *(uint32_t*)&p;
}
#define SW128(o) ((o) ^ (((o) >> 3) & 0x70))

#define LDSM_X4(r0, r1, r2, r3, addr) \
    asm volatile("ldmatrix.sync.aligned.m8n8.x4.shared.b16 {%0,%1,%2,%3}, [%4];" \
                 : "=r"(r0), "=r"(r1), "=r"(r2), "=r"(r3) : "r"(addr))
#define LDSM_X4T(r0, r1, r2, r3, addr) \
    asm volatile("ldmatrix.sync.aligned.m8n8.x4.trans.shared.b16 {%0,%1,%2,%3}, [%4];" \
                 : "=r"(r0), "=r"(r1), "=r"(r2), "=r"(r3) : "r"(addr))
#define MMA16816F16(d, a, b) \
    asm volatile("mma.sync.aligned.m16n8k16.row.col.f32.f16.f16.f32 " \
                 "{%0,%1,%2,%3}, {%4,%5,%6,%7}, {%8,%9}, {%0,%1,%2,%3};" \
                 : "+f"((d)[0]), "+f"((d)[1]), "+f"((d)[2]), "+f"((d)[3]) \
                 : "r"((a)[0]), "r"((a)[1]), "r"((a)[2]), "r"((a)[3]), \
                   "r"((b)[0]), "r"((b)[1]))
#define CP16(dst, src) \
    asm volatile("cp.async.cg.shared.global [%0], [%1], 16;" :: "r"(dst), "l"(src))
#define CP_COMMIT() asm volatile("cp.async.commit_group;" ::: "memory")
#define CP_WAIT1()  asm volatile("cp.async.wait_group 1;" ::: "memory")
#define CP_WAIT0()  asm volatile("cp.async.wait_group 0;" ::: "memory")

// ============================================================================
// Front kernel: dispatcher [convert_A | convert_W | weight frag bake]
// ============================================================================
#define A_BLOCKS  2048
#define W_BLOCKS  704
#define FH_BLOCKS 64

__global__ __launch_bounds__(256) void k_front(
    const float* __restrict__ x, const float* __restrict__ f,
    const float* __restrict__ Wep1, const float* __restrict__ Wp1,
    const float* __restrict__ W2)
{
    const int t = threadIdx.x;
    const int bid = blockIdx.x;

    if (bid < A_BLOCKS) {
        // ---- convert A: single fp16 plane, source read once ----
        int idx = bid * 256 + t;                 // over 2048*256
        int m = idx >> 8;
        int k = (idx & 255) * 8;
        const float* src = (k < 1024) ? (x + (size_t)m * 1024 + k)
                                      : (f + (size_t)m * 1024 + (k - 1024));
        float4 f0 = *(const float4*)src;
        float4 f1 = *(const float4*)(src + 4);
        float vv[8] = {f0.x, f0.y, f0.z, f0.w, f1.x, f1.y, f1.z, f1.w};
        union { __half h[8]; uint4 u; } H;
#pragma unroll
        for (int e = 0; e < 8; ++e) H.h[e] = __float2half(vv[e]);
        *(uint4*)(g_Ah + (size_t)m * 2048 + k) = H.u;
    } else if (bid < A_BLOCKS + W_BLOCKS) {
        // ---- convert W: [2048 k][704 n] fp16; 0-511 Wep1, 512-671 Wp1, pad 0 ----
        int idx = (bid - A_BLOCKS) * 256 + t;    // over 2048*88
        int k = idx / 88;
        int n = (idx - k * 88) * 8;
        float vv[8];
        if (n < 512) {
            float4 w0 = *(const float4*)&Wep1[(size_t)k * 512 + n];
            float4 w1 = *(const float4*)&Wep1[(size_t)k * 512 + n + 4];
            vv[0] = w0.x; vv[1] = w0.y; vv[2] = w0.z; vv[3] = w0.w;
            vv[4] = w1.x; vv[5] = w1.y; vv[6] = w1.z; vv[7] = w1.w;
        } else if (n < 672) {
#pragma unroll
            for (int e = 0; e < 8; ++e) {
                int u = n + e - 512, en = u / 5, r = u - en * 5;
                vv[e] = (k < 1024) ? Wp1[en * 5120 + k * 5 + r] : 0.f;
            }
        } else {
#pragma unroll
            for (int e = 0; e < 8; ++e) vv[e] = 0.f;
        }
        union { __half h[8]; uint4 u; } O;
#pragma unroll
        for (int e = 0; e < 8; ++e) O.h[e] = __float2half(vv[e]);
        *(uint4*)(g_Bh + (size_t)k * NPAD + n) = O.u;
    } else {
        // ---- bake weight fragments: one uint32 per thread, frag-ordered ----
        int gid = (bid - A_BLOCKS - W_BLOCKS) * 256 + t;   // over 16384
        int e = gid & 8191;
        int idx = e & 15;            // position in the thread's 16-reg frag set
        int wl = e >> 4;             // 0..511 = warp*32 + lane
        int w = wl >> 5, l = wl & 31;
        int gr = l >> 2, c2 = (l & 3) * 2;
        if (gid < 8192) {
            // bw1[nch][s][r]: idx = nch*4 + s*2 + r
            int nch = idx >> 2, s = (idx >> 1) & 1, r = idx & 1;
            int n = w * 32 + nch * 8 + gr;
            int row = s * 16 + c2 + r * 8;
            const float* W1z = Wep1 + 2048 * 512;
            g_W1zf[wl * 16 + idx] = packh2(__float2half(W1z[row * 512 + n]),
                                           __float2half(W1z[(row + 1) * 512 + n]));
        } else {
            // bw2[kst][r]: idx = kst*2 + r; warp w -> ks=w>>2, nch=w&3
            int kst = idx >> 1, r = idx & 1;
            int k = (w >> 2) * 128 + kst * 16 + c2 + r * 8;
            int n = (w & 3) * 8 + gr;
            g_W2f[wl * 16 + idx] = packh2(__float2half(W2[k * 32 + n]),
                                          __float2half(W2[(k + 1) * 32 + n]));
        }
    }
}

// ============================================================================
// HMMA GEMM (fp16 single-product): D[2048,704] = A[2048,2048] @ B[2048,704].
// BM=128 BN=64 BK=64, 256 thr (8 warps, 32x32 warp tiles), 2-stage cp.async.
// ============================================================================
__device__ __forceinline__ void gemm_issue(int tid, int m0, int n0, int chunk,
                                           uint32_t sb, int stage) {
    const __half* Ah = g_Ah + (size_t)m0 * 2048 + chunk * 64;
    const __half* Bb = g_Bh + (size_t)chunk * 64 * NPAD + n0;
    uint32_t sA = sb + stage * 24576;
    uint32_t sB = sA + 16384;
#pragma unroll
    for (int i = 0; i < 4; ++i) {
        int v = tid * 4 + i, m = v >> 3, q = v & 7;
        uint32_t so = SW128((uint32_t)(m * 128 + q * 16));
        CP16(sA + so, Ah + (size_t)m * 2048 + q * 8);
    }
#pragma unroll
    for (int i = 0; i < 2; ++i) {
        int v = tid * 2 + i, kr = v >> 3, q = v & 7;
        uint32_t so = SW128((uint32_t)(kr * 128 + q * 16));
        CP16(sB + so, Bb + (size_t)kr * NPAD + q * 8);
    }
}

__global__ __launch_bounds__(256, 2) void k_gemm() {
    extern __shared__ __align__(1024) char smem[];
    const uint32_t sb = smem_u32(smem);
    const int tid = threadIdx.x, lane = tid & 31, wid = tid >> 5;
    const int m0 = blockIdx.y * 128;
    const int n0 = blockIdx.x * 64;
    const int c0 = blockIdx.z * 11;
    const int nc = (blockIdx.z == 2) ? 10 : 11;
    const int warp_m = (wid & 3) * 32;
    const int warp_n = (wid >> 2) * 32;

    float acc[2][4][4] = {};

    gemm_issue(tid, m0, n0, c0, sb, 0); CP_COMMIT();

    for (int ci = 0; ci < nc; ++ci) {
        if (ci + 1 < nc) {
            gemm_issue(tid, m0, n0, c0 + ci + 1, sb, (ci + 1) & 1);
            CP_COMMIT();
            CP_WAIT1();
        } else {
            CP_WAIT0();
        }
        __syncthreads();

        const uint32_t sA = sb + (ci & 1) * 24576;
        const uint32_t sB = sA + 16384;
#pragma unroll
        for (int s = 0; s < 4; ++s) {
            uint32_t aH[2][4], bF[4][2];
            const int kh = s * 16 + (lane >> 4) * 8;
#pragma unroll
            for (int i = 0; i < 2; ++i) {
                int row = warp_m + i * 16 + ((lane >> 3) & 1) * 8 + (lane & 7);
                uint32_t so = SW128((uint32_t)(row * 128 + kh * 2));
                LDSM_X4(aH[i][0], aH[i][1], aH[i][2], aH[i][3], sA + so);
            }
            const int kr = s * 16 + ((lane >> 3) & 1) * 8 + (lane & 7);
#pragma unroll
            for (int j2 = 0; j2 < 2; ++j2) {
                int ncol = warp_n + j2 * 16 + (lane >> 4) * 8;
                uint32_t bd = sB + SW128((uint32_t)(kr * 128 + ncol * 2));
                LDSM_X4T(bF[j2 * 2][0], bF[j2 * 2][1],
                         bF[j2 * 2 + 1][0], bF[j2 * 2 + 1][1], bd);
            }
#pragma unroll
            for (int i = 0; i < 2; ++i)
#pragma unroll
                for (int j = 0; j < 4; ++j)
                    MMA16816F16(acc[i][j], aH[i], bF[j]);
        }
        __syncthreads();
    }

    float* dst = g_part + (size_t)blockIdx.z * PART2;
#pragma unroll
    for (int i = 0; i < 2; ++i)
#pragma unroll
        for (int j = 0; j < 4; ++j) {
            int r = m0 + warp_m + i * 16 + (lane >> 2);
            int cC = n0 + warp_n + j * 8 + (lane & 3) * 2;
            *(float2*)&dst[(size_t)r * NPAD + cC] = make_float2(acc[i][j][0], acc[i][j][1]);
            *(float2*)&dst[(size_t)(r + 8) * NPAD + cC] = make_float2(acc[i][j][2], acc[i][j][3]);
        }
}

// ============================================================================
// Tensor-core tail: 256 blocks x 4 row-batches of 16 (b,n) rows, 512 thr.
// Weight frags loaded once per block (registers), reused across batches.
// ============================================================================
#define ZSTR 36
#define HSTR 520

__global__ __launch_bounds__(512, 2) void k_tail(
    const float* __restrict__ z, const float* __restrict__ bep1,
    const float* __restrict__ bep2,
    const float* __restrict__ bp1, const float* __restrict__ Wp2,
    const float* __restrict__ bp2, const float* __restrict__ Wp3,
    const float* __restrict__ bp3, float* __restrict__ out)
{
    extern __shared__ float dsm[];
    float* zs     = dsm;                        // [16][ZSTR]
    float* base_s = dsm + 16 * ZSTR;            // [2][512]
    float* ps     = base_s + 1024;              // [64]
    float* gbuf   = ps + 64;                    // [4][16][32]
    __half* hs_hi = (__half*)(gbuf + 2048);     // [16][HSTR]
    __half* hs_lo = hs_hi + 16 * HSTR;          // [16][HSTR]

    const int t = threadIdx.x;
    const int lane = t & 31, w = t >> 5;
    const int gr = lane >> 2, c2 = (lane & 3) * 2;

    // pre-baked weight frags: 4+4 LDG.128 per thread, once per block
    uint32_t bw1[16], bw2[16];
    {
        const uint4* p1 = (const uint4*)(g_W1zf + t * 16);
        const uint4* p2 = (const uint4*)(g_W2f + t * 16);
#pragma unroll
        for (int q = 0; q < 4; ++q) {
            *(uint4*)&bw1[q * 4] = p1[q];
            *(uint4*)&bw2[q * 4] = p2[q];
        }
    }

    for (int it = 0; it < 4; ++it) {
        const int r0 = (blockIdx.x * 4 + it) * 16;
        const int b0 = (blockIdx.x * 4 + it) * 2;

        {   // z tile + base rows (coalesced)
            const int row = t >> 5, o = t & 31;
            zs[row * ZSTR + o] = z[(size_t)(r0 + row) * 32 + o];
            base_s[t]       = g_part[(size_t)b0 * NPAD + t]
                            + g_part[PART2 + (size_t)b0 * NPAD + t]
                            + g_part[2 * PART2 + (size_t)b0 * NPAD + t] + bep1[t];
            base_s[512 + t] = g_part[(size_t)(b0 + 1) * NPAD + t]
                            + g_part[PART2 + (size_t)(b0 + 1) * NPAD + t]
                            + g_part[2 * PART2 + (size_t)(b0 + 1) * NPAD + t] + bep1[t];
        }
        __syncthreads();

        // ---- phase A: T1[16,512] = z[16,32] @ W1z[32,512]; warp w: n-slice ----
        {
            const int wn = w * 32;
            uint32_t aH[2][4], aL[2][4];
#pragma unroll
            for (int s = 0; s < 2; ++s)
#pragma unroll
                for (int hk = 0; hk < 2; ++hk)
#pragma unroll
                    for (int rr = 0; rr < 2; ++rr) {
                        float2 v = *(float2*)&zs[(gr + rr * 8) * ZSTR + s * 16 + hk * 8 + c2];
                        __half h0 = __float2half(v.x), h1 = __float2half(v.y);
                        int ri = hk * 2 + rr;
                        aH[s][ri] = packh2(h0, h1);
                        aL[s][ri] = packh2(__float2half(v.x - __half2float(h0)),
                                           __float2half(v.y - __half2float(h1)));
                    }
            float cfr[4][4] = {};
#pragma unroll
            for (int nch = 0; nch < 4; ++nch)
#pragma unroll
                for (int s = 0; s < 2; ++s) {
                    uint32_t* bb = &bw1[nch * 4 + s * 2];
                    MMA16816F16(cfr[nch], aH[s], bb);
                    MMA16816F16(cfr[nch], aL[s], bb);
                }
#pragma unroll
            for (int nch = 0; nch < 4; ++nch) {
                int j = wn + nch * 8 + c2;
                float v00 = fmaxf(cfr[nch][0] + base_s[j], 0.f);
                float v01 = fmaxf(cfr[nch][1] + base_s[j + 1], 0.f);
                float v10 = fmaxf(cfr[nch][2] + base_s[512 + j], 0.f);
                float v11 = fmaxf(cfr[nch][3] + base_s[512 + j + 1], 0.f);
                __half a0 = __float2half(v00), a1 = __float2half(v01);
                __half b0h = __float2half(v10), b1h = __float2half(v11);
                *(uint32_t*)&hs_hi[gr * HSTR + j] = packh2(a0, a1);
                *(uint32_t*)&hs_lo[gr * HSTR + j] =
                    packh2(__float2half(v00 - __half2float(a0)),
                           __float2half(v01 - __half2float(a1)));
                *(uint32_t*)&hs_hi[(gr + 8) * HSTR + j] = packh2(b0h, b1h);
                *(uint32_t*)&hs_lo[(gr + 8) * HSTR + j] =
                    packh2(__float2half(v10 - __half2float(b0h)),
                           __float2half(v11 - __half2float(b1h)));
            }
        }
        __syncthreads();

        // ---- phase B: G[16,32] = h[16,512] @ W2[512,32]; warp=(kslice,nchunk) ----
        {
            const int ks = w >> 2, nch = w & 3;
            float gfr[4] = {};
#pragma unroll
            for (int kst = 0; kst < 8; ++kst) {
                int k = ks * 128 + kst * 16;
                uint32_t aH2[4], aL2[4];
                aH2[0] = *(uint32_t*)&hs_hi[gr * HSTR + k + c2];
                aH2[1] = *(uint32_t*)&hs_hi[(gr + 8) * HSTR + k + c2];
                aH2[2] = *(uint32_t*)&hs_hi[gr * HSTR + k + c2 + 8];
                aH2[3] = *(uint32_t*)&hs_hi[(gr + 8) * HSTR + k + c2 + 8];
                aL2[0] = *(uint32_t*)&hs_lo[gr * HSTR + k + c2];
                aL2[1] = *(uint32_t*)&hs_lo[(gr + 8) * HSTR + k + c2];
                aL2[2] = *(uint32_t*)&hs_lo[gr * HSTR + k + c2 + 8];
                aL2[3] = *(uint32_t*)&hs_lo[(gr + 8) * HSTR + k + c2 + 8];
                uint32_t* bb = &bw2[kst * 2];
                MMA16816F16(gfr, aH2, bb);
                MMA16816F16(gfr, aL2, bb);
            }
            int o = nch * 8 + c2;
            *(float2*)&gbuf[(ks * 16 + gr) * 32 + o] = make_float2(gfr[0], gfr[1]);
            *(float2*)&gbuf[(ks * 16 + gr + 8) * 32 + o] = make_float2(gfr[2], gfr[3]);
        }

        // prior ensemble layers 2-3 (64 threads; g_part L2-warm)
        if (t < 64) {
            const int bb = b0 + (t >> 5), e = t & 31;
            const size_t off = (size_t)bb * NPAD + 512 + e * 5;
            float s1[5];
#pragma unroll
            for (int k = 0; k < 5; ++k)
                s1[k] = fmaxf(g_part[off + k] + g_part[PART2 + off + k]
                              + g_part[2 * PART2 + off + k] + bp1[e * 5 + k], 0.f);
            float p = bp3[e];
#pragma unroll
            for (int g = 0; g < 5; ++g) {
                float s = bp2[e * 5 + g];
#pragma unroll
                for (int k = 0; k < 5; ++k) s += s1[k] * Wp2[e * 25 + k * 5 + g];
                p += fmaxf(s, 0.f) * Wp3[e * 5 + g];
            }
            ps[t] = p;
        }
        __syncthreads();

        // ---- final: out[row] = sum_o (G+bep2+p)*z ; warp w = row, lane = o ----
        {
            const int row = w, o = lane;
            float g = gbuf[row * 32 + o] + gbuf[512 + row * 32 + o]
                    + gbuf[1024 + row * 32 + o] + gbuf[1536 + row * 32 + o];
            float val = (g + bep2[o] + ps[(row >> 3) * 32 + o]) * zs[row * ZSTR + o];
#pragma unroll
            for (int off = 16; off > 0; off >>= 1)
                val += __shfl_xor_sync(0xffffffffu, val, off);
            if (o == 0) out[r0 + row] = val;
        }
        __syncthreads();   // protect smem reuse across row-batches
    }
}

// ============================================================================
extern "C" void kernel_launch(void* const* d_in, const int* in_sizes, int n_in,
                              void* d_out, int out_size)
{
    const float* x    = (const float*)d_in[0];
    const float* feat = (const float*)d_in[1];
    const float* z    = (const float*)d_in[2];
    const float* Wep1 = (const float*)d_in[3];
    const float* bep1 = (const float*)d_in[4];
    const float* Wep2 = (const float*)d_in[5];
    const float* bep2 = (const float*)d_in[6];
    const float* Wp1  = (const float*)d_in[7];
    const float* bp1  = (const float*)d_in[8];
    const float* Wp2  = (const float*)d_in[9];
    const float* bp2  = (const float*)d_in[10];
    const float* Wp3  = (const float*)d_in[11];
    const float* bp3  = (const float*)d_in[12];
    float* out = (float*)d_out;

    const int tail_smem = (16 * ZSTR + 1024 + 64 + 2048) * 4 + 2 * 16 * HSTR * 2;

    static int smem_set = 0;
    if (!smem_set) {
        cudaFuncSetAttribute(k_gemm, cudaFuncAttributeMaxDynamicSharedMemorySize, 49152);
        cudaFuncSetAttribute(k_tail, cudaFuncAttributeMaxDynamicSharedMemorySize, 50000);
        smem_set = 1;
    }

    k_front<<<A_BLOCKS + W_BLOCKS + FH_BLOCKS, 256>>>(x, feat, Wep1, Wp1, Wep2);
    k_gemm<<<dim3(11, 16, 3), 256, 49152>>>();
    k_tail<<<256, 512, tail_smem>>>(z, bep1, bep2, bp1, Wp2, bp2, Wp3, bp3, out);
}

// round 17
// speedup vs baseline: 1.1524x; 1.1524x over previous
#include <cuda_runtime.h>
#include <cuda_fp16.h>
#include <cstdint>

typedef unsigned long long ULL;

#define NPAD 704
#define PART2 (2048L * NPAD)

// ---------------- scratch (static device arrays; no runtime alloc) ----------
__device__ __half g_Ah[2048L * 2048];          // fp16 of concat(x,feature)  8MB
__device__ __half g_Bh[2048L * NPAD];          // fp16 [Wep1^T | Wp1 fold | 0]
__device__ float g_part[4 * PART2];            // K-split partial outputs
__device__ uint32_t g_W1zf[512 * 16];          // frag-ordered W1z (per warp/lane)
__device__ uint32_t g_W2f[512 * 16];           // frag-ordered Wep2

// ---------------- helpers ----------------------------------------------------
__device__ __forceinline__ uint32_t smem_u32(const void* p) {
    uint32_t a;
    asm("{ .reg .u64 t; cvta.to.shared.u64 t, %1; cvt.u32.u64 %0, t; }" : "=r"(a) : "l"(p));
    return a;
}
__device__ __forceinline__ uint32_t packh2(__half a, __half b) {
    __half2 p = __halves2half2(a, b);
    return *(uint32_t*)&p;
}
#define SW128(o) ((o) ^ (((o) >> 3) & 0x70))

#define LDSM_X4(r0, r1, r2, r3, addr) \
    asm volatile("ldmatrix.sync.aligned.m8n8.x4.shared.b16 {%0,%1,%2,%3}, [%4];" \
                 : "=r"(r0), "=r"(r1), "=r"(r2), "=r"(r3) : "r"(addr))
#define LDSM_X4T(r0, r1, r2, r3, addr) \
    asm volatile("ldmatrix.sync.aligned.m8n8.x4.trans.shared.b16 {%0,%1,%2,%3}, [%4];" \
                 : "=r"(r0), "=r"(r1), "=r"(r2), "=r"(r3) : "r"(addr))
#define MMA16816F16(d, a, b) \
    asm volatile("mma.sync.aligned.m16n8k16.row.col.f32.f16.f16.f32 " \
                 "{%0,%1,%2,%3}, {%4,%5,%6,%7}, {%8,%9}, {%0,%1,%2,%3};" \
                 : "+f"((d)[0]), "+f"((d)[1]), "+f"((d)[2]), "+f"((d)[3]) \
                 : "r"((a)[0]), "r"((a)[1]), "r"((a)[2]), "r"((a)[3]), \
                   "r"((b)[0]), "r"((b)[1]))
#define CP16(dst, src) \
    asm volatile("cp.async.cg.shared.global [%0], [%1], 16;" :: "r"(dst), "l"(src))
#define CP_COMMIT() asm volatile("cp.async.commit_group;" ::: "memory")
#define CP_WAIT1()  asm volatile("cp.async.wait_group 1;" ::: "memory")
#define CP_WAIT0()  asm volatile("cp.async.wait_group 0;" ::: "memory")

// ============================================================================
// Front kernel: dispatcher [convert_A | convert_W | weight frag bake]
// ============================================================================
#define A_BLOCKS  2048
#define W_BLOCKS  704
#define FH_BLOCKS 64

__global__ __launch_bounds__(256) void k_front(
    const float* __restrict__ x, const float* __restrict__ f,
    const float* __restrict__ Wep1, const float* __restrict__ Wp1,
    const float* __restrict__ W2)
{
    const int t = threadIdx.x;
    const int bid = blockIdx.x;

    if (bid < A_BLOCKS) {
        // ---- convert A: single fp16 plane, source read once ----
        int idx = bid * 256 + t;                 // over 2048*256
        int m = idx >> 8;
        int k = (idx & 255) * 8;
        const float* src = (k < 1024) ? (x + (size_t)m * 1024 + k)
                                      : (f + (size_t)m * 1024 + (k - 1024));
        float4 f0 = *(const float4*)src;
        float4 f1 = *(const float4*)(src + 4);
        float vv[8] = {f0.x, f0.y, f0.z, f0.w, f1.x, f1.y, f1.z, f1.w};
        union { __half h[8]; uint4 u; } H;
#pragma unroll
        for (int e = 0; e < 8; ++e) H.h[e] = __float2half(vv[e]);
        *(uint4*)(g_Ah + (size_t)m * 2048 + k) = H.u;
    } else if (bid < A_BLOCKS + W_BLOCKS) {
        // ---- convert W: [2048 k][704 n] fp16; 0-511 Wep1, 512-671 Wp1, pad 0 ----
        int idx = (bid - A_BLOCKS) * 256 + t;    // over 2048*88
        int k = idx / 88;
        int n = (idx - k * 88) * 8;
        float vv[8];
        if (n < 512) {
            float4 w0 = *(const float4*)&Wep1[(size_t)k * 512 + n];
            float4 w1 = *(const float4*)&Wep1[(size_t)k * 512 + n + 4];
            vv[0] = w0.x; vv[1] = w0.y; vv[2] = w0.z; vv[3] = w0.w;
            vv[4] = w1.x; vv[5] = w1.y; vv[6] = w1.z; vv[7] = w1.w;
        } else if (n < 672) {
#pragma unroll
            for (int e = 0; e < 8; ++e) {
                int u = n + e - 512, en = u / 5, r = u - en * 5;
                vv[e] = (k < 1024) ? Wp1[en * 5120 + k * 5 + r] : 0.f;
            }
        } else {
#pragma unroll
            for (int e = 0; e < 8; ++e) vv[e] = 0.f;
        }
        union { __half h[8]; uint4 u; } O;
#pragma unroll
        for (int e = 0; e < 8; ++e) O.h[e] = __float2half(vv[e]);
        *(uint4*)(g_Bh + (size_t)k * NPAD + n) = O.u;
    } else {
        // ---- bake weight fragments: one uint32 per thread, frag-ordered ----
        int gid = (bid - A_BLOCKS - W_BLOCKS) * 256 + t;   // over 16384
        int e = gid & 8191;
        int idx = e & 15;            // position in the thread's 16-reg frag set
        int wl = e >> 4;             // 0..511 = warp*32 + lane
        int w = wl >> 5, l = wl & 31;
        int gr = l >> 2, c2 = (l & 3) * 2;
        if (gid < 8192) {
            // bw1[nch][s][r]: idx = nch*4 + s*2 + r
            int nch = idx >> 2, s = (idx >> 1) & 1, r = idx & 1;
            int n = w * 32 + nch * 8 + gr;
            int row = s * 16 + c2 + r * 8;
            const float* W1z = Wep1 + 2048 * 512;
            g_W1zf[wl * 16 + idx] = packh2(__float2half(W1z[row * 512 + n]),
                                           __float2half(W1z[(row + 1) * 512 + n]));
        } else {
            // bw2[kst][r]: idx = kst*2 + r; warp w -> ks=w>>2, nch=w&3
            int kst = idx >> 1, r = idx & 1;
            int k = (w >> 2) * 128 + kst * 16 + c2 + r * 8;
            int n = (w & 3) * 8 + gr;
            g_W2f[wl * 16 + idx] = packh2(__float2half(W2[k * 32 + n]),
                                          __float2half(W2[(k + 1) * 32 + n]));
        }
    }
}

// ============================================================================
// HMMA GEMM (fp16): D[2048,704] = A[2048,2048] @ B[2048,704].
// BM=128 BN=64 BK=64, 256 thr (8 warps, 32x32 warp tiles), 2-stage cp.async.
// 4-way K-split of 8 chunks; splits z>=2 (k>=1024) skip n>=512 (B is zero).
// ============================================================================
__device__ __forceinline__ void gemm_issue(int tid, int m0, int n0, int chunk,
                                           uint32_t sb, int stage) {
    const __half* Ah = g_Ah + (size_t)m0 * 2048 + chunk * 64;
    const __half* Bb = g_Bh + (size_t)chunk * 64 * NPAD + n0;
    uint32_t sA = sb + stage * 24576;
    uint32_t sB = sA + 16384;
#pragma unroll
    for (int i = 0; i < 4; ++i) {
        int v = tid * 4 + i, m = v >> 3, q = v & 7;
        uint32_t so = SW128((uint32_t)(m * 128 + q * 16));
        CP16(sA + so, Ah + (size_t)m * 2048 + q * 8);
    }
#pragma unroll
    for (int i = 0; i < 2; ++i) {
        int v = tid * 2 + i, kr = v >> 3, q = v & 7;
        uint32_t so = SW128((uint32_t)(kr * 128 + q * 16));
        CP16(sB + so, Bb + (size_t)kr * NPAD + q * 8);
    }
}

__global__ __launch_bounds__(256, 2) void k_gemm() {
    const int n0 = blockIdx.x * 64;
    const int zi = blockIdx.z;
    if (zi >= 2 && n0 >= 512) return;        // B zero for k>=1024, n>=512

    extern __shared__ __align__(1024) char smem[];
    const uint32_t sb = smem_u32(smem);
    const int tid = threadIdx.x, lane = tid & 31, wid = tid >> 5;
    const int m0 = blockIdx.y * 128;
    const int c0 = zi * 8;
    const int warp_m = (wid & 3) * 32;
    const int warp_n = (wid >> 2) * 32;

    float acc[2][4][4] = {};

    gemm_issue(tid, m0, n0, c0, sb, 0); CP_COMMIT();

    for (int ci = 0; ci < 8; ++ci) {
        if (ci + 1 < 8) {
            gemm_issue(tid, m0, n0, c0 + ci + 1, sb, (ci + 1) & 1);
            CP_COMMIT();
            CP_WAIT1();
        } else {
            CP_WAIT0();
        }
        __syncthreads();

        const uint32_t sA = sb + (ci & 1) * 24576;
        const uint32_t sB = sA + 16384;
#pragma unroll
        for (int s = 0; s < 4; ++s) {
            uint32_t aH[2][4], bF[4][2];
            const int kh = s * 16 + (lane >> 4) * 8;
#pragma unroll
            for (int i = 0; i < 2; ++i) {
                int row = warp_m + i * 16 + ((lane >> 3) & 1) * 8 + (lane & 7);
                uint32_t so = SW128((uint32_t)(row * 128 + kh * 2));
                LDSM_X4(aH[i][0], aH[i][1], aH[i][2], aH[i][3], sA + so);
            }
            const int kr = s * 16 + ((lane >> 3) & 1) * 8 + (lane & 7);
#pragma unroll
            for (int j2 = 0; j2 < 2; ++j2) {
                int ncol = warp_n + j2 * 16 + (lane >> 4) * 8;
                uint32_t bd = sB + SW128((uint32_t)(kr * 128 + ncol * 2));
                LDSM_X4T(bF[j2 * 2][0], bF[j2 * 2][1],
                         bF[j2 * 2 + 1][0], bF[j2 * 2 + 1][1], bd);
            }
#pragma unroll
            for (int i = 0; i < 2; ++i)
#pragma unroll
                for (int j = 0; j < 4; ++j)
                    MMA16816F16(acc[i][j], aH[i], bF[j]);
        }
        __syncthreads();
    }

    float* dst = g_part + (size_t)zi * PART2;
#pragma unroll
    for (int i = 0; i < 2; ++i)
#pragma unroll
        for (int j = 0; j < 4; ++j) {
            int r = m0 + warp_m + i * 16 + (lane >> 2);
            int cC = n0 + warp_n + j * 8 + (lane & 3) * 2;
            *(float2*)&dst[(size_t)r * NPAD + cC] = make_float2(acc[i][j][0], acc[i][j][1]);
            *(float2*)&dst[(size_t)(r + 8) * NPAD + cC] = make_float2(acc[i][j][2], acc[i][j][3]);
        }
}

// ============================================================================
// Tensor-core tail (R15 shape): 1024 blocks, 16 (b,n) rows each, 512 thr.
// base = sum of 4 partials (n<512); prior h1 = sum of partials 0,1 (k<1024).
// ============================================================================
#define ZSTR 36
#define HSTR 520

__global__ __launch_bounds__(512, 2) void k_tail(
    const float* __restrict__ z, const float* __restrict__ bep1,
    const float* __restrict__ bep2,
    const float* __restrict__ bp1, const float* __restrict__ Wp2,
    const float* __restrict__ bp2, const float* __restrict__ Wp3,
    const float* __restrict__ bp3, float* __restrict__ out)
{
    extern __shared__ float dsm[];
    float* zs     = dsm;                        // [16][ZSTR]
    float* base_s = dsm + 16 * ZSTR;            // [2][512]
    float* ps     = base_s + 1024;              // [64]
    float* gbuf   = ps + 64;                    // [4][16][32]
    __half* hs_hi = (__half*)(gbuf + 2048);     // [16][HSTR]
    __half* hs_lo = hs_hi + 16 * HSTR;          // [16][HSTR]

    const int t = threadIdx.x;
    const int lane = t & 31, w = t >> 5;
    const int gr = lane >> 2, c2 = (lane & 3) * 2;
    const int r0 = blockIdx.x * 16;
    const int b0 = blockIdx.x * 2;

    // pre-baked weight frags: 4+4 LDG.128 per thread
    uint32_t bw1[16], bw2[16];
    {
        const uint4* p1 = (const uint4*)(g_W1zf + t * 16);
        const uint4* p2 = (const uint4*)(g_W2f + t * 16);
#pragma unroll
        for (int q = 0; q < 4; ++q) {
            *(uint4*)&bw1[q * 4] = p1[q];
            *(uint4*)&bw2[q * 4] = p2[q];
        }
    }

    {   // z tile + base rows (coalesced); base = 4 partials
        const int row = t >> 5, o = t & 31;
        zs[row * ZSTR + o] = z[(size_t)(r0 + row) * 32 + o];
        float b0v = bep1[t], b1v = b0v;
#pragma unroll
        for (int s = 0; s < 4; ++s) {
            b0v += g_part[s * PART2 + (size_t)b0 * NPAD + t];
            b1v += g_part[s * PART2 + (size_t)(b0 + 1) * NPAD + t];
        }
        base_s[t] = b0v;
        base_s[512 + t] = b1v;
    }
    __syncthreads();

    // ---- phase A: T1[16,512] = z[16,32] @ W1z[32,512], warp w: n-slice w*32 ----
    {
        const int wn = w * 32;
        uint32_t aH[2][4], aL[2][4];
#pragma unroll
        for (int s = 0; s < 2; ++s)
#pragma unroll
            for (int hk = 0; hk < 2; ++hk)
#pragma unroll
                for (int rr = 0; rr < 2; ++rr) {
                    float2 v = *(float2*)&zs[(gr + rr * 8) * ZSTR + s * 16 + hk * 8 + c2];
                    __half h0 = __float2half(v.x), h1 = __float2half(v.y);
                    int ri = hk * 2 + rr;
                    aH[s][ri] = packh2(h0, h1);
                    aL[s][ri] = packh2(__float2half(v.x - __half2float(h0)),
                                       __float2half(v.y - __half2float(h1)));
                }
        float cfr[4][4] = {};
#pragma unroll
        for (int nch = 0; nch < 4; ++nch)
#pragma unroll
            for (int s = 0; s < 2; ++s) {
                uint32_t* bb = &bw1[nch * 4 + s * 2];
                MMA16816F16(cfr[nch], aH[s], bb);
                MMA16816F16(cfr[nch], aL[s], bb);
            }
#pragma unroll
        for (int nch = 0; nch < 4; ++nch) {
            int j = wn + nch * 8 + c2;
            float v00 = fmaxf(cfr[nch][0] + base_s[j], 0.f);
            float v01 = fmaxf(cfr[nch][1] + base_s[j + 1], 0.f);
            float v10 = fmaxf(cfr[nch][2] + base_s[512 + j], 0.f);
            float v11 = fmaxf(cfr[nch][3] + base_s[512 + j + 1], 0.f);
            __half a0 = __float2half(v00), a1 = __float2half(v01);
            __half b0h = __float2half(v10), b1h = __float2half(v11);
            *(uint32_t*)&hs_hi[gr * HSTR + j] = packh2(a0, a1);
            *(uint32_t*)&hs_lo[gr * HSTR + j] =
                packh2(__float2half(v00 - __half2float(a0)),
                       __float2half(v01 - __half2float(a1)));
            *(uint32_t*)&hs_hi[(gr + 8) * HSTR + j] = packh2(b0h, b1h);
            *(uint32_t*)&hs_lo[(gr + 8) * HSTR + j] =
                packh2(__float2half(v10 - __half2float(b0h)),
                       __float2half(v11 - __half2float(b1h)));
        }
    }
    __syncthreads();

    // ---- phase B: G[16,32] = h[16,512] @ W2[512,32]; warp = (kslice, nchunk) ----
    {
        const int ks = w >> 2, nch = w & 3;
        float gfr[4] = {};
#pragma unroll
        for (int kst = 0; kst < 8; ++kst) {
            int k = ks * 128 + kst * 16;
            uint32_t aH2[4], aL2[4];
            aH2[0] = *(uint32_t*)&hs_hi[gr * HSTR + k + c2];
            aH2[1] = *(uint32_t*)&hs_hi[(gr + 8) * HSTR + k + c2];
            aH2[2] = *(uint32_t*)&hs_hi[gr * HSTR + k + c2 + 8];
            aH2[3] = *(uint32_t*)&hs_hi[(gr + 8) * HSTR + k + c2 + 8];
            aL2[0] = *(uint32_t*)&hs_lo[gr * HSTR + k + c2];
            aL2[1] = *(uint32_t*)&hs_lo[(gr + 8) * HSTR + k + c2];
            aL2[2] = *(uint32_t*)&hs_lo[gr * HSTR + k + c2 + 8];
            aL2[3] = *(uint32_t*)&hs_lo[(gr + 8) * HSTR + k + c2 + 8];
            uint32_t* bb = &bw2[kst * 2];
            MMA16816F16(gfr, aH2, bb);
            MMA16816F16(gfr, aL2, bb);
        }
        int o = nch * 8 + c2;
        *(float2*)&gbuf[(ks * 16 + gr) * 32 + o] = make_float2(gfr[0], gfr[1]);
        *(float2*)&gbuf[(ks * 16 + gr + 8) * 32 + o] = make_float2(gfr[2], gfr[3]);
    }

    // prior ensemble layers 2-3 (64 threads; partials 0,1 cover k<1024)
    if (t < 64) {
        const int bb = b0 + (t >> 5), e = t & 31;
        const size_t off = (size_t)bb * NPAD + 512 + e * 5;
        float s1[5];
#pragma unroll
        for (int k = 0; k < 5; ++k)
            s1[k] = fmaxf(g_part[off + k] + g_part[PART2 + off + k]
                          + bp1[e * 5 + k], 0.f);
        float p = bp3[e];
#pragma unroll
        for (int g = 0; g < 5; ++g) {
            float s = bp2[e * 5 + g];
#pragma unroll
            for (int k = 0; k < 5; ++k) s += s1[k] * Wp2[e * 25 + k * 5 + g];
            p += fmaxf(s, 0.f) * Wp3[e * 5 + g];
        }
        ps[t] = p;
    }
    __syncthreads();

    // ---- final: out[row] = sum_o (G+bep2+p)*z ; warp w = row, lane = o ----
    {
        const int row = w, o = lane;
        float g = gbuf[row * 32 + o] + gbuf[512 + row * 32 + o]
                + gbuf[1024 + row * 32 + o] + gbuf[1536 + row * 32 + o];
        float val = (g + bep2[o] + ps[(row >> 3) * 32 + o]) * zs[row * ZSTR + o];
#pragma unroll
        for (int off = 16; off > 0; off >>= 1)
            val += __shfl_xor_sync(0xffffffffu, val, off);
        if (o == 0) out[r0 + row] = val;
    }
}

// ============================================================================
extern "C" void kernel_launch(void* const* d_in, const int* in_sizes, int n_in,
                              void* d_out, int out_size)
{
    const float* x    = (const float*)d_in[0];
    const float* feat = (const float*)d_in[1];
    const float* z    = (const float*)d_in[2];
    const float* Wep1 = (const float*)d_in[3];
    const float* bep1 = (const float*)d_in[4];
    const float* Wep2 = (const float*)d_in[5];
    const float* bep2 = (const float*)d_in[6];
    const float* Wp1  = (const float*)d_in[7];
    const float* bp1  = (const float*)d_in[8];
    const float* Wp2  = (const float*)d_in[9];
    const float* bp2  = (const float*)d_in[10];
    const float* Wp3  = (const float*)d_in[11];
    const float* bp3  = (const float*)d_in[12];
    float* out = (float*)d_out;

    const int tail_smem = (16 * ZSTR + 1024 + 64 + 2048) * 4 + 2 * 16 * HSTR * 2;

    static int smem_set = 0;
    if (!smem_set) {
        cudaFuncSetAttribute(k_gemm, cudaFuncAttributeMaxDynamicSharedMemorySize, 49152);
        cudaFuncSetAttribute(k_tail, cudaFuncAttributeMaxDynamicSharedMemorySize, 50000);
        smem_set = 1;
    }

    k_front<<<A_BLOCKS + W_BLOCKS + FH_BLOCKS, 256>>>(x, feat, Wep1, Wp1, Wep2);
    k_gemm<<<dim3(11, 16, 4), 256, 49152>>>();
    k_tail<<<1024, 512, tail_smem>>>(z, bep1, bep2, bp1, Wp2, bp2, Wp3, bp3, out);
}